// round 3
// baseline (speedup 1.0000x reference)
#include <cuda_runtime.h>
#include <math.h>

// ---------------------------------------------------------------------------
// FraudGraphSAGE: 2-layer GraphSAGE (mean agg) + FC sigmoid head.
//   h1 = relu(mean_agg(x) @ W1l + x @ W1r + b1)
//   h2 = relu(mean_agg(h1) @ W2l + h1 @ W2r + b2)
//   out = sigmoid(h2 @ Wfc + bfc)
// ---------------------------------------------------------------------------

#define NMAX 100000

// float4-typed to guarantee 16B alignment (plain float arrays get .align 4)
__device__ float4 g_agg4[(size_t)NMAX * 32];
__device__ float4 g_h14[(size_t)NMAX * 32];
__device__ float4 g_deg4[(NMAX + 3) / 4];
__device__ float  g_invdeg[NMAX];
__device__ int    g_idx_is64;

// ---------------------------------------------------------------------------
// Probe edge_index dtype: int64 values < 2^32 have zero high words; int32
// pairs reinterpreted as 64-bit almost surely have nonzero high words.
// ---------------------------------------------------------------------------
__global__ void probe_kernel(const void* ei)
{
    const unsigned long long* p = (const unsigned long long*)ei;
    int is64 = 1;
    for (int i = 0; i < 8; i++)
        if (p[i] >> 32) { is64 = 0; break; }
    g_idx_is64 = is64;
}

__device__ __forceinline__ int2 load_edge(const void* ei, int E, int e, int is64)
{
    if (is64) {
        const long long* p = (const long long*)ei;
        return make_int2((int)__ldg(p + e), (int)__ldg(p + E + e));
    } else {
        const int* p = (const int*)ei;
        return make_int2(__ldg(p + e), __ldg(p + E + e));
    }
}

// ---------------------------------------------------------------------------
// Zero scratch buffers (agg always; deg optionally)
// ---------------------------------------------------------------------------
__global__ void zero_all_kernel(int n, int alsoDeg)
{
    int tid = blockIdx.x * blockDim.x + threadIdx.x;
    int stride = gridDim.x * blockDim.x;
    float4 z = make_float4(0.f, 0.f, 0.f, 0.f);
    int t = n * 32;   // n*128 floats / 4
    for (int i = tid; i < t; i += stride) g_agg4[i] = z;
    if (alsoDeg) {
        int td = (n + 3) / 4;
        for (int i = tid; i < td; i += stride) g_deg4[i] = z;
    }
}

// ---------------------------------------------------------------------------
// Degree count + inverse degree
// ---------------------------------------------------------------------------
__global__ void deg_kernel(const void* __restrict__ ei, int E)
{
    int is64 = g_idx_is64;
    float* deg = (float*)g_deg4;
    int tid = blockIdx.x * blockDim.x + threadIdx.x;
    int stride = gridDim.x * blockDim.x;
    for (int i = tid; i < E; i += stride) {
        int d;
        if (is64) d = (int)__ldg(((const long long*)ei) + E + i);
        else      d = __ldg(((const int*)ei) + E + i);
        atomicAdd(&deg[d], 1.0f);
    }
}

__global__ void invdeg_kernel(int n)
{
    const float* deg = (const float*)g_deg4;
    int i = blockIdx.x * blockDim.x + threadIdx.x;
    if (i < n) g_invdeg[i] = 1.0f / fmaxf(deg[i], 1.0f);
}

// ---------------------------------------------------------------------------
// Scatter: agg[dst] += feat[src]   (one warp per edge)
// Each lane loads 16B of the source row and issues 4 scalar atomicAdds at
// consecutive addresses -> 4 fully-coalesced RED waves per edge-warp.
// ---------------------------------------------------------------------------
__global__ void scatter_kernel(const float* __restrict__ feat,
                               const void* __restrict__ ei, int E)
{
    int is64 = g_idx_is64;
    float* agg = (float*)g_agg4;
    int lane = threadIdx.x & 31;
    int warp = (blockIdx.x * blockDim.x + threadIdx.x) >> 5;
    int nwarp = (gridDim.x * blockDim.x) >> 5;
    const float4* f4 = (const float4*)feat;
    for (int e = warp; e < E; e += nwarp) {
        int2 sd = load_edge(ei, E, e, is64);
        float4 v = __ldg(f4 + (size_t)sd.x * 32 + lane);
        float* p = agg + (size_t)sd.y * 128 + lane * 4;
        atomicAdd(p + 0, v.x);
        atomicAdd(p + 1, v.y);
        atomicAdd(p + 2, v.z);
        atomicAdd(p + 3, v.w);
    }
}

// ---------------------------------------------------------------------------
// Fused dual-GEMM:
//   C[i][c] = relu( (agg[i]*invdeg[i]) @ Wl + A2[i] @ Wr + bias )
// EPI==0: store C rows (h).   EPI==1: out[i] = sigmoid(C[i] @ wfc + bfc).
//
// 512 threads/CTA, BM=128 rows, all 128 cols. Full combined weights (256x128
// f32 = 128KB) resident in SMEM. A staged in double-buffered SMEM chunks of
// 32 k-values, stored transposed As[k][row] (stride 132) with an XOR swizzle
// (row ^ 4*(k>>2)) making the transpose store conflict-free while keeping
// 16B-aligned row-group reads. Accumulators packed row-pairs in f32x2; the
// inner loop is 16 fma.rn.f32x2 + 3 LDS + 4 MOV per k -> FMA-pipe bound.
// ---------------------------------------------------------------------------
#define GEMM_SMEM_FLOATS (256 * 128 + 128 + 128 + 2 * 4224)
#define GEMM_SMEM_BYTES  (GEMM_SMEM_FLOATS * 4)

template <int EPI>
__global__ __launch_bounds__(512, 1)
void gemm_kernel(const float* __restrict__ A2,
                 const float* __restrict__ Wl, const float* __restrict__ Wr,
                 const float* __restrict__ bias,
                 const float* __restrict__ wfc, const float* __restrict__ bfc,
                 float* __restrict__ out, int n)
{
    extern __shared__ float smem[];
    float* Ws = smem;              // 256*128
    float* bs = Ws + 256 * 128;    // 128
    float* fs = bs + 128;          // 128
    float* As = fs + 128;          // 2 * 4224 (32 * 132 each)

    const int tid = threadIdx.x;
    const int tx = tid & 31;
    const int ty = tid >> 5;
    const int rowBase = blockIdx.x * 128;
    const float* A1 = (const float*)g_agg4;

    // stage weights: rows 0..127 = Wl, 128..255 = Wr
    {
        const float4* wl4 = (const float4*)Wl;
        const float4* wr4 = (const float4*)Wr;
        float4* ws4 = (float4*)Ws;
#pragma unroll
        for (int j = 0; j < 8; j++) {
            int idx = tid + 512 * j;
            ws4[idx] = __ldg(wl4 + idx);
            ws4[4096 + idx] = __ldg(wr4 + idx);
        }
    }
    if (tid < 128) {
        bs[tid] = bias[tid];
        fs[tid] = EPI ? wfc[tid] : 0.f;
    }

    // loader mapping: thread loads rows (lrow) and (lrow+64), 4 k-values each
    const int lrow = tid >> 3;   // 0..63
    const int lk4 = tid & 7;     // 0..7
    const int gr0 = rowBase + lrow;
    const int gr1 = rowBase + 64 + lrow;
    const float id0 = (gr0 < n) ? g_invdeg[gr0] : 1.f;
    const float id1 = (gr1 < n) ? g_invdeg[gr1] : 1.f;

    unsigned long long acc[4][4];
#pragma unroll
    for (int p = 0; p < 4; p++)
#pragma unroll
        for (int c = 0; c < 4; c++) acc[p][c] = 0ull;

    auto loadA = [&](int kc, float4& a, float4& b) {
        const float* src = (kc < 4) ? A1 : A2;
        int koff = ((kc < 4) ? kc : kc - 4) * 32 + 4 * lk4;
        a = (gr0 < n) ? *(const float4*)(src + (size_t)gr0 * 128 + koff)
                      : make_float4(0.f, 0.f, 0.f, 0.f);
        b = (gr1 < n) ? *(const float4*)(src + (size_t)gr1 * 128 + koff)
                      : make_float4(0.f, 0.f, 0.f, 0.f);
    };
    auto storeA = [&](int kc, float4 a, float4 b, float* buf) {
        if (kc < 4) {
            a.x *= id0; a.y *= id0; a.z *= id0; a.w *= id0;
            b.x *= id1; b.y *= id1; b.z *= id1; b.w *= id1;
        }
        int sw = 4 * lk4;
        int r0 = lrow ^ sw;
        int r1 = (64 + lrow) ^ sw;
        float av[4] = {a.x, a.y, a.z, a.w};
        float bv[4] = {b.x, b.y, b.z, b.w};
#pragma unroll
        for (int c = 0; c < 4; c++) {
            buf[(4 * lk4 + c) * 132 + r0] = av[c];
            buf[(4 * lk4 + c) * 132 + r1] = bv[c];
        }
    };

    float4 va, vb;
    loadA(0, va, vb);
    storeA(0, va, vb, As);
    __syncthreads();

    for (int kc = 0; kc < 8; kc++) {
        const float* cur = As + (kc & 1) * 4224;
        float4 na, nb;
        if (kc < 7) loadA(kc + 1, na, nb);
        const float* wbase = Ws + (kc * 32) * 128 + 4 * tx;
#pragma unroll 8
        for (int k = 0; k < 32; k++) {
            int sw = (k >> 2) << 2;
            const float* ak = cur + k * 132;
            ulonglong2 aA = *(const ulonglong2*)(ak + ((8 * ty) ^ sw));
            ulonglong2 aB = *(const ulonglong2*)(ak + ((8 * ty + 4) ^ sw));
            float4 w = *(const float4*)(wbase + k * 128);
            unsigned long long ap[4] = {aA.x, aA.y, aB.x, aB.y};
            unsigned long long wd[4];
            unsigned int wx = __float_as_uint(w.x), wy = __float_as_uint(w.y);
            unsigned int wz = __float_as_uint(w.z), ww = __float_as_uint(w.w);
            asm("mov.b64 %0, {%1,%1};" : "=l"(wd[0]) : "r"(wx));
            asm("mov.b64 %0, {%1,%1};" : "=l"(wd[1]) : "r"(wy));
            asm("mov.b64 %0, {%1,%1};" : "=l"(wd[2]) : "r"(wz));
            asm("mov.b64 %0, {%1,%1};" : "=l"(wd[3]) : "r"(ww));
#pragma unroll
            for (int p = 0; p < 4; p++)
#pragma unroll
                for (int c = 0; c < 4; c++)
                    asm("fma.rn.f32x2 %0, %1, %2, %0;"
                        : "+l"(acc[p][c]) : "l"(ap[p]), "l"(wd[c]));
        }
        if (kc < 7) storeA(kc + 1, na, nb, As + ((kc + 1) & 1) * 4224);
        __syncthreads();
    }

    // epilogue: unpack row pairs, +bias, relu
    float v[8][4];
#pragma unroll
    for (int p = 0; p < 4; p++)
#pragma unroll
        for (int c = 0; c < 4; c++) {
            unsigned int lo, hi;
            asm("mov.b64 {%0,%1}, %2;" : "=r"(lo), "=r"(hi) : "l"(acc[p][c]));
            float bb = bs[4 * tx + c];
            v[2 * p][c]     = fmaxf(__uint_as_float(lo) + bb, 0.f);
            v[2 * p + 1][c] = fmaxf(__uint_as_float(hi) + bb, 0.f);
        }

    if (EPI == 0) {
#pragma unroll
        for (int lr = 0; lr < 8; lr++) {
            int gr = rowBase + 8 * ty + lr;
            if (gr < n)
                *(float4*)(out + (size_t)gr * 128 + 4 * tx) =
                    make_float4(v[lr][0], v[lr][1], v[lr][2], v[lr][3]);
        }
    } else {
        float wf0 = fs[4 * tx], wf1 = fs[4 * tx + 1];
        float wf2 = fs[4 * tx + 2], wf3 = fs[4 * tx + 3];
        float bv = __ldg(bfc);
#pragma unroll
        for (int lr = 0; lr < 8; lr++) {
            float s = v[lr][0] * wf0 + v[lr][1] * wf1 + v[lr][2] * wf2 + v[lr][3] * wf3;
#pragma unroll
            for (int off = 16; off; off >>= 1)
                s += __shfl_xor_sync(0xffffffffu, s, off);
            int gr = rowBase + 8 * ty + lr;
            if (tx == 0 && gr < n)
                out[gr] = 1.0f / (1.0f + __expf(-(s + bv)));
        }
    }
}

// ---------------------------------------------------------------------------
// Launch sequence
// ---------------------------------------------------------------------------
extern "C" void kernel_launch(void* const* d_in, const int* in_sizes, int n_in,
                              void* d_out, int out_size)
{
    const float* x   = (const float*)d_in[0];
    const void*  ei  = d_in[1];
    const float* W1l = (const float*)d_in[2];
    const float* W1r = (const float*)d_in[3];
    const float* b1  = (const float*)d_in[4];
    const float* W2l = (const float*)d_in[5];
    const float* W2r = (const float*)d_in[6];
    const float* b2  = (const float*)d_in[7];
    const float* Wfc = (const float*)d_in[8];
    const float* bfc = (const float*)d_in[9];
    float*       out = (float*)d_out;

    int n = in_sizes[0] / 128;
    int E = in_sizes[1] / 2;

    float* h1_ptr = nullptr;
    cudaGetSymbolAddress((void**)&h1_ptr, g_h14);

    cudaFuncSetAttribute(gemm_kernel<0>,
                         cudaFuncAttributeMaxDynamicSharedMemorySize, GEMM_SMEM_BYTES);
    cudaFuncSetAttribute(gemm_kernel<1>,
                         cudaFuncAttributeMaxDynamicSharedMemorySize, GEMM_SMEM_BYTES);

    int gemmBlocks = (n + 127) / 128;

    // dtype probe + deg + invdeg (same for both layers)
    probe_kernel<<<1, 1>>>(ei);
    zero_all_kernel<<<2048, 256>>>(n, 1);
    deg_kernel<<<1024, 256>>>(ei, E);
    invdeg_kernel<<<(n + 255) / 256, 256>>>(n);

    // layer 1
    scatter_kernel<<<4096, 256>>>(x, ei, E);
    gemm_kernel<0><<<gemmBlocks, 512, GEMM_SMEM_BYTES>>>(
        x, W1l, W1r, b1, nullptr, nullptr, h1_ptr, n);

    // layer 2 + FC head
    zero_all_kernel<<<2048, 256>>>(n, 0);
    scatter_kernel<<<4096, 256>>>(h1_ptr, ei, E);
    gemm_kernel<1><<<gemmBlocks, 512, GEMM_SMEM_BYTES>>>(
        h1_ptr, W2l, W2r, b2, Wfc, bfc, out, n);
}

// round 4
// speedup vs baseline: 1.5942x; 1.5942x over previous
#include <cuda_runtime.h>
#include <math.h>

// ---------------------------------------------------------------------------
// FraudGraphSAGE: 2-layer GraphSAGE (mean agg) + FC sigmoid head.
//   h1 = relu(mean_agg(x) @ W1l + x @ W1r + b1)
//   h2 = relu(mean_agg(h1) @ W2l + h1 @ W2r + b2)
//   out = sigmoid(h2 @ Wfc + bfc)
// Aggregation via CSR gather (no f32 atomics).
// ---------------------------------------------------------------------------

#define NMAX 100000
#define EMAX 1000000
#define NBLK ((NMAX + 255) / 256)   // 391 <= 512

// float4-typed to guarantee 16B alignment
__device__ float4 g_agg4[(size_t)NMAX * 32];
__device__ float4 g_h14[(size_t)NMAX * 32];
__device__ int    g_degi[NMAX];
__device__ int    g_rowptr[NMAX];
__device__ int    g_fill[NMAX];
__device__ int    g_csr[EMAX];
__device__ int    g_blocksum[NBLK + 1];
__device__ int    g_blockoff[NBLK + 1];
__device__ int    g_idx_is64;

// ---------------------------------------------------------------------------
// Probe edge_index dtype: int64 < 2^32 has zero high words; int32 pairs
// reinterpreted as 64-bit almost surely have nonzero high words.
// ---------------------------------------------------------------------------
__global__ void probe_kernel(const void* ei)
{
    const unsigned long long* p = (const unsigned long long*)ei;
    int is64 = 1;
    for (int i = 0; i < 8; i++)
        if (p[i] >> 32) { is64 = 0; break; }
    g_idx_is64 = is64;
}

__device__ __forceinline__ int edge_dst(const void* ei, int E, int e, int is64)
{
    if (is64) return (int)__ldg(((const long long*)ei) + E + e);
    return __ldg(((const int*)ei) + E + e);
}
__device__ __forceinline__ int edge_src(const void* ei, int E, int e, int is64)
{
    if (is64) return (int)__ldg(((const long long*)ei) + e);
    return __ldg(((const int*)ei) + e);
}

// ---------------------------------------------------------------------------
// CSR build: degree -> exclusive scan -> fill
// ---------------------------------------------------------------------------
__global__ void zero_meta_kernel(int n)
{
    int i = blockIdx.x * blockDim.x + threadIdx.x;
    if (i < n) { g_degi[i] = 0; g_fill[i] = 0; }
}

__global__ void deg_kernel(const void* __restrict__ ei, int E)
{
    int is64 = g_idx_is64;
    int tid = blockIdx.x * blockDim.x + threadIdx.x;
    int stride = gridDim.x * blockDim.x;
    for (int i = tid; i < E; i += stride)
        atomicAdd(&g_degi[edge_dst(ei, E, i, is64)], 1);
}

__global__ void block_sums_kernel(int n)
{
    __shared__ int sh[256];
    int i = blockIdx.x * 256 + threadIdx.x;
    sh[threadIdx.x] = (i < n) ? g_degi[i] : 0;
    __syncthreads();
#pragma unroll
    for (int s = 128; s; s >>= 1) {
        if (threadIdx.x < s) sh[threadIdx.x] += sh[threadIdx.x + s];
        __syncthreads();
    }
    if (threadIdx.x == 0) g_blocksum[blockIdx.x] = sh[0];
}

__global__ void scan_sums_kernel(int nb)
{
    __shared__ int sh[512];
    int t = threadIdx.x;
    int v = (t < nb) ? g_blocksum[t] : 0;
    sh[t] = v;
    __syncthreads();
#pragma unroll
    for (int off = 1; off < 512; off <<= 1) {
        int x = (t >= off) ? sh[t - off] : 0;
        __syncthreads();
        sh[t] += x;
        __syncthreads();
    }
    if (t < nb) g_blockoff[t] = sh[t] - v;   // exclusive
}

__global__ void scan_block_kernel(int n)
{
    __shared__ int sh[256];
    int i = blockIdx.x * 256 + threadIdx.x;
    int v = (i < n) ? g_degi[i] : 0;
    sh[threadIdx.x] = v;
    __syncthreads();
#pragma unroll
    for (int off = 1; off < 256; off <<= 1) {
        int x = (threadIdx.x >= off) ? sh[threadIdx.x - off] : 0;
        __syncthreads();
        sh[threadIdx.x] += x;
        __syncthreads();
    }
    if (i < n) g_rowptr[i] = sh[threadIdx.x] - v + g_blockoff[blockIdx.x];
}

__global__ void fill_kernel(const void* __restrict__ ei, int E)
{
    int is64 = g_idx_is64;
    int tid = blockIdx.x * blockDim.x + threadIdx.x;
    int stride = gridDim.x * blockDim.x;
    for (int e = tid; e < E; e += stride) {
        int d = edge_dst(ei, E, e, is64);
        int s = edge_src(ei, E, e, is64);
        int pos = g_rowptr[d] + atomicAdd(&g_fill[d], 1);
        g_csr[pos] = s;
    }
}

// ---------------------------------------------------------------------------
// Gather: agg[i] = mean_{j in N(i)} feat[j].  One warp per node; 4-deep
// independent accumulators for MLP; writes the mean directly (no atomics).
// ---------------------------------------------------------------------------
__global__ void gather_kernel(const float* __restrict__ feat, int n)
{
    int lane = threadIdx.x & 31;
    int w = (blockIdx.x * blockDim.x + threadIdx.x) >> 5;
    if (w >= n) return;
    int start = g_rowptr[w];
    int cnt = g_degi[w];
    const float4* f4 = (const float4*)feat;
    float4 a0 = make_float4(0.f, 0.f, 0.f, 0.f), a1 = a0, a2 = a0, a3 = a0;
    int j = 0;
    for (; j + 4 <= cnt; j += 4) {
        int s0 = __ldg(g_csr + start + j);
        int s1 = __ldg(g_csr + start + j + 1);
        int s2 = __ldg(g_csr + start + j + 2);
        int s3 = __ldg(g_csr + start + j + 3);
        float4 v0 = __ldg(f4 + (size_t)s0 * 32 + lane);
        float4 v1 = __ldg(f4 + (size_t)s1 * 32 + lane);
        float4 v2 = __ldg(f4 + (size_t)s2 * 32 + lane);
        float4 v3 = __ldg(f4 + (size_t)s3 * 32 + lane);
        a0.x += v0.x; a0.y += v0.y; a0.z += v0.z; a0.w += v0.w;
        a1.x += v1.x; a1.y += v1.y; a1.z += v1.z; a1.w += v1.w;
        a2.x += v2.x; a2.y += v2.y; a2.z += v2.z; a2.w += v2.w;
        a3.x += v3.x; a3.y += v3.y; a3.z += v3.z; a3.w += v3.w;
    }
    for (; j < cnt; j++) {
        int s = __ldg(g_csr + start + j);
        float4 v = __ldg(f4 + (size_t)s * 32 + lane);
        a0.x += v.x; a0.y += v.y; a0.z += v.z; a0.w += v.w;
    }
    float inv = 1.0f / fmaxf((float)cnt, 1.0f);
    float4 r;
    r.x = (a0.x + a1.x + a2.x + a3.x) * inv;
    r.y = (a0.y + a1.y + a2.y + a3.y) * inv;
    r.z = (a0.z + a1.z + a2.z + a3.z) * inv;
    r.w = (a0.w + a1.w + a2.w + a3.w) * inv;
    g_agg4[(size_t)w * 32 + lane] = r;
}

// ---------------------------------------------------------------------------
// Fused dual-GEMM: C[i] = relu( agg[i] @ Wl + A2[i] @ Wr + bias )
// EPI==0: store C rows.  EPI==1: out[i] = sigmoid(C[i] @ wfc + bfc).
// 512 thr/CTA, 128 rows, full combined weights (128KB) in SMEM, A double-
// buffered transposed+swizzled, f32x2 packed accumulators (FMA-pipe bound).
// ---------------------------------------------------------------------------
#define GEMM_SMEM_FLOATS (256 * 128 + 128 + 128 + 2 * 4224)
#define GEMM_SMEM_BYTES  (GEMM_SMEM_FLOATS * 4)

template <int EPI>
__global__ __launch_bounds__(512, 1)
void gemm_kernel(const float* __restrict__ A2,
                 const float* __restrict__ Wl, const float* __restrict__ Wr,
                 const float* __restrict__ bias,
                 const float* __restrict__ wfc, const float* __restrict__ bfc,
                 float* __restrict__ out, int n)
{
    extern __shared__ float smem[];
    float* Ws = smem;              // 256*128
    float* bs = Ws + 256 * 128;    // 128
    float* fs = bs + 128;          // 128
    float* As = fs + 128;          // 2 * 4224 (32 * 132 each)

    const int tid = threadIdx.x;
    const int tx = tid & 31;
    const int ty = tid >> 5;
    const int rowBase = blockIdx.x * 128;
    const float* A1 = (const float*)g_agg4;

    {
        const float4* wl4 = (const float4*)Wl;
        const float4* wr4 = (const float4*)Wr;
        float4* ws4 = (float4*)Ws;
#pragma unroll
        for (int j = 0; j < 8; j++) {
            int idx = tid + 512 * j;
            ws4[idx] = __ldg(wl4 + idx);
            ws4[4096 + idx] = __ldg(wr4 + idx);
        }
    }
    if (tid < 128) {
        bs[tid] = bias[tid];
        fs[tid] = EPI ? wfc[tid] : 0.f;
    }

    const int lrow = tid >> 3;   // 0..63
    const int lk4 = tid & 7;     // 0..7
    const int gr0 = rowBase + lrow;
    const int gr1 = rowBase + 64 + lrow;

    unsigned long long acc[4][4];
#pragma unroll
    for (int p = 0; p < 4; p++)
#pragma unroll
        for (int c = 0; c < 4; c++) acc[p][c] = 0ull;

    auto loadA = [&](int kc, float4& a, float4& b) {
        const float* src = (kc < 4) ? A1 : A2;
        int koff = ((kc < 4) ? kc : kc - 4) * 32 + 4 * lk4;
        a = (gr0 < n) ? *(const float4*)(src + (size_t)gr0 * 128 + koff)
                      : make_float4(0.f, 0.f, 0.f, 0.f);
        b = (gr1 < n) ? *(const float4*)(src + (size_t)gr1 * 128 + koff)
                      : make_float4(0.f, 0.f, 0.f, 0.f);
    };
    auto storeA = [&](float4 a, float4 b, float* buf) {
        int sw = 4 * lk4;
        int r0 = lrow ^ sw;
        int r1 = (64 + lrow) ^ sw;
        float av[4] = {a.x, a.y, a.z, a.w};
        float bv[4] = {b.x, b.y, b.z, b.w};
#pragma unroll
        for (int c = 0; c < 4; c++) {
            buf[(4 * lk4 + c) * 132 + r0] = av[c];
            buf[(4 * lk4 + c) * 132 + r1] = bv[c];
        }
    };

    float4 va, vb;
    loadA(0, va, vb);
    storeA(va, vb, As);
    __syncthreads();

    for (int kc = 0; kc < 8; kc++) {
        const float* cur = As + (kc & 1) * 4224;
        float4 na, nb;
        if (kc < 7) loadA(kc + 1, na, nb);
        const float* wbase = Ws + (kc * 32) * 128 + 4 * tx;
#pragma unroll 8
        for (int k = 0; k < 32; k++) {
            int sw = (k >> 2) << 2;
            const float* ak = cur + k * 132;
            ulonglong2 aA = *(const ulonglong2*)(ak + ((8 * ty) ^ sw));
            ulonglong2 aB = *(const ulonglong2*)(ak + ((8 * ty + 4) ^ sw));
            float4 w = *(const float4*)(wbase + k * 128);
            unsigned long long ap[4] = {aA.x, aA.y, aB.x, aB.y};
            unsigned long long wd[4];
            unsigned int wx = __float_as_uint(w.x), wy = __float_as_uint(w.y);
            unsigned int wz = __float_as_uint(w.z), ww = __float_as_uint(w.w);
            asm("mov.b64 %0, {%1,%1};" : "=l"(wd[0]) : "r"(wx));
            asm("mov.b64 %0, {%1,%1};" : "=l"(wd[1]) : "r"(wy));
            asm("mov.b64 %0, {%1,%1};" : "=l"(wd[2]) : "r"(wz));
            asm("mov.b64 %0, {%1,%1};" : "=l"(wd[3]) : "r"(ww));
#pragma unroll
            for (int p = 0; p < 4; p++)
#pragma unroll
                for (int c = 0; c < 4; c++)
                    asm("fma.rn.f32x2 %0, %1, %2, %0;"
                        : "+l"(acc[p][c]) : "l"(ap[p]), "l"(wd[c]));
        }
        if (kc < 7) storeA(na, nb, As + ((kc + 1) & 1) * 4224);
        __syncthreads();
    }

    float v[8][4];
#pragma unroll
    for (int p = 0; p < 4; p++)
#pragma unroll
        for (int c = 0; c < 4; c++) {
            unsigned int lo, hi;
            asm("mov.b64 {%0,%1}, %2;" : "=r"(lo), "=r"(hi) : "l"(acc[p][c]));
            float bb = bs[4 * tx + c];
            v[2 * p][c]     = fmaxf(__uint_as_float(lo) + bb, 0.f);
            v[2 * p + 1][c] = fmaxf(__uint_as_float(hi) + bb, 0.f);
        }

    if (EPI == 0) {
#pragma unroll
        for (int lr = 0; lr < 8; lr++) {
            int gr = rowBase + 8 * ty + lr;
            if (gr < n)
                *(float4*)(out + (size_t)gr * 128 + 4 * tx) =
                    make_float4(v[lr][0], v[lr][1], v[lr][2], v[lr][3]);
        }
    } else {
        float wf0 = fs[4 * tx], wf1 = fs[4 * tx + 1];
        float wf2 = fs[4 * tx + 2], wf3 = fs[4 * tx + 3];
        float bv = __ldg(bfc);
#pragma unroll
        for (int lr = 0; lr < 8; lr++) {
            float s = v[lr][0] * wf0 + v[lr][1] * wf1 + v[lr][2] * wf2 + v[lr][3] * wf3;
#pragma unroll
            for (int off = 16; off; off >>= 1)
                s += __shfl_xor_sync(0xffffffffu, s, off);
            int gr = rowBase + 8 * ty + lr;
            if (tx == 0 && gr < n)
                out[gr] = 1.0f / (1.0f + __expf(-(s + bv)));
        }
    }
}

// ---------------------------------------------------------------------------
// Launch sequence
// ---------------------------------------------------------------------------
extern "C" void kernel_launch(void* const* d_in, const int* in_sizes, int n_in,
                              void* d_out, int out_size)
{
    const float* x   = (const float*)d_in[0];
    const void*  ei  = d_in[1];
    const float* W1l = (const float*)d_in[2];
    const float* W1r = (const float*)d_in[3];
    const float* b1  = (const float*)d_in[4];
    const float* W2l = (const float*)d_in[5];
    const float* W2r = (const float*)d_in[6];
    const float* b2  = (const float*)d_in[7];
    const float* Wfc = (const float*)d_in[8];
    const float* bfc = (const float*)d_in[9];
    float*       out = (float*)d_out;

    int n = in_sizes[0] / 128;
    int E = in_sizes[1] / 2;

    float* h1_ptr = nullptr;
    cudaGetSymbolAddress((void**)&h1_ptr, g_h14);

    cudaFuncSetAttribute(gemm_kernel<0>,
                         cudaFuncAttributeMaxDynamicSharedMemorySize, GEMM_SMEM_BYTES);
    cudaFuncSetAttribute(gemm_kernel<1>,
                         cudaFuncAttributeMaxDynamicSharedMemorySize, GEMM_SMEM_BYTES);

    int gemmBlocks = (n + 127) / 128;
    int nb = (n + 255) / 256;
    int gatherBlocks = (n * 32 + 255) / 256;

    // CSR build (once)
    probe_kernel<<<1, 1>>>(ei);
    zero_meta_kernel<<<nb, 256>>>(n);
    deg_kernel<<<1024, 256>>>(ei, E);
    block_sums_kernel<<<nb, 256>>>(n);
    scan_sums_kernel<<<1, 512>>>(nb);
    scan_block_kernel<<<nb, 256>>>(n);
    fill_kernel<<<1024, 256>>>(ei, E);

    // layer 1
    gather_kernel<<<gatherBlocks, 256>>>(x, n);
    gemm_kernel<0><<<gemmBlocks, 512, GEMM_SMEM_BYTES>>>(
        x, W1l, W1r, b1, nullptr, nullptr, h1_ptr, n);

    // layer 2 + FC head
    gather_kernel<<<gatherBlocks, 256>>>(h1_ptr, n);
    gemm_kernel<1><<<gemmBlocks, 512, GEMM_SMEM_BYTES>>>(
        h1_ptr, W2l, W2r, b2, Wfc, bfc, out, n);
}

// round 6
// speedup vs baseline: 1.7438x; 1.0938x over previous
#include <cuda_runtime.h>
#include <cuda_bf16.h>
#include <math.h>
#include <stdint.h>

// ---------------------------------------------------------------------------
// FraudGraphSAGE: 2-layer GraphSAGE (mean agg) + FC sigmoid head.
// Aggregation: CSR gather (no f32 atomics).
// GEMMs: mma.sync m16n8k16 bf16-split (hi/lo), fp32 accumulate.
// (tcgen05 unavailable: harness compiles via compute_103 PTX, not sm_103a.)
// ---------------------------------------------------------------------------

#define NMAX 100000
#define EMAX 1000000
#define NBLK ((NMAX + 255) / 256)

__device__ float4 g_agg4[(size_t)NMAX * 32];
__device__ float4 g_h14[(size_t)NMAX * 32];
__device__ int    g_degi[NMAX];
__device__ int    g_rowptr[NMAX];
__device__ int    g_fill[NMAX];
__device__ int    g_csr[EMAX];
__device__ int    g_blocksum[NBLK + 1];
__device__ int    g_blockoff[NBLK + 1];
__device__ int    g_idx_is64;
// W images: [layer][hi=0/lo=1][69632B]: [n=128][k_perm=256 pad->272] bf16
__device__ uint4  g_wimg[2][2][4352];

// ======================= helpers ===========================================
__device__ __forceinline__ uint32_t smem_u32(const void* p) {
    uint32_t a;
    asm("{ .reg .u64 t; cvta.to.shared.u64 t, %1; cvt.u32.u64 %0, t; }"
        : "=r"(a) : "l"(p));
    return a;
}
__device__ __forceinline__ void lds64(uint32_t& x, uint32_t& y, uint32_t addr) {
    asm volatile("ld.shared.v2.b32 {%0,%1}, [%2];" : "=r"(x), "=r"(y) : "r"(addr));
}
__device__ __forceinline__ void mma_bf16(float* c, uint32_t a0, uint32_t a1,
                                         uint32_t a2, uint32_t a3,
                                         uint32_t b0, uint32_t b1) {
    asm volatile(
        "mma.sync.aligned.m16n8k16.row.col.f32.bf16.bf16.f32 "
        "{%0,%1,%2,%3}, {%4,%5,%6,%7}, {%8,%9}, {%0,%1,%2,%3};"
        : "+f"(c[0]), "+f"(c[1]), "+f"(c[2]), "+f"(c[3])
        : "r"(a0), "r"(a1), "r"(a2), "r"(a3), "r"(b0), "r"(b1));
}

// ======================= dtype probe + CSR build ===========================
__global__ void probe_kernel(const void* ei)
{
    const unsigned long long* p = (const unsigned long long*)ei;
    int is64 = 1;
    for (int i = 0; i < 8; i++)
        if (p[i] >> 32) { is64 = 0; break; }
    g_idx_is64 = is64;
}

__device__ __forceinline__ int edge_dst(const void* ei, int E, int e, int is64)
{
    if (is64) return (int)__ldg(((const long long*)ei) + E + e);
    return __ldg(((const int*)ei) + E + e);
}
__device__ __forceinline__ int edge_src(const void* ei, int E, int e, int is64)
{
    if (is64) return (int)__ldg(((const long long*)ei) + e);
    return __ldg(((const int*)ei) + e);
}

__global__ void zero_meta_kernel(int n)
{
    int i = blockIdx.x * blockDim.x + threadIdx.x;
    if (i < n) { g_degi[i] = 0; g_fill[i] = 0; }
}

__global__ void deg_kernel(const void* __restrict__ ei, int E)
{
    int is64 = g_idx_is64;
    int tid = blockIdx.x * blockDim.x + threadIdx.x;
    int stride = gridDim.x * blockDim.x;
    for (int i = tid; i < E; i += stride)
        atomicAdd(&g_degi[edge_dst(ei, E, i, is64)], 1);
}

__global__ void block_sums_kernel(int n)
{
    __shared__ int sh[256];
    int i = blockIdx.x * 256 + threadIdx.x;
    sh[threadIdx.x] = (i < n) ? g_degi[i] : 0;
    __syncthreads();
#pragma unroll
    for (int s = 128; s; s >>= 1) {
        if (threadIdx.x < s) sh[threadIdx.x] += sh[threadIdx.x + s];
        __syncthreads();
    }
    if (threadIdx.x == 0) g_blocksum[blockIdx.x] = sh[0];
}

__global__ void scan_sums_kernel(int nb)
{
    __shared__ int sh[512];
    int t = threadIdx.x;
    int v = (t < nb) ? g_blocksum[t] : 0;
    sh[t] = v;
    __syncthreads();
#pragma unroll
    for (int off = 1; off < 512; off <<= 1) {
        int x = (t >= off) ? sh[t - off] : 0;
        __syncthreads();
        sh[t] += x;
        __syncthreads();
    }
    if (t < nb) g_blockoff[t] = sh[t] - v;
}

__global__ void scan_block_kernel(int n)
{
    __shared__ int sh[256];
    int i = blockIdx.x * 256 + threadIdx.x;
    int v = (i < n) ? g_degi[i] : 0;
    sh[threadIdx.x] = v;
    __syncthreads();
#pragma unroll
    for (int off = 1; off < 256; off <<= 1) {
        int x = (threadIdx.x >= off) ? sh[threadIdx.x - off] : 0;
        __syncthreads();
        sh[threadIdx.x] += x;
        __syncthreads();
    }
    if (i < n) g_rowptr[i] = sh[threadIdx.x] - v + g_blockoff[blockIdx.x];
}

__global__ void fill_kernel(const void* __restrict__ ei, int E)
{
    int is64 = g_idx_is64;
    int tid = blockIdx.x * blockDim.x + threadIdx.x;
    int stride = gridDim.x * blockDim.x;
    for (int e = tid; e < E; e += stride) {
        int d = edge_dst(ei, E, e, is64);
        int s = edge_src(ei, E, e, is64);
        int pos = g_rowptr[d] + atomicAdd(&g_fill[d], 1);
        g_csr[pos] = s;
    }
}

// ======================= W prep: split + transposed k-perm image ===========
// image[n][pos]: pos = ks*16 + 4*((kp&7)>>1) + 2*(kp>>3) + (kp&1),
// where ks=k>>4, kp=k&15. Row stride 272 bf16 (544B).
__global__ void prep_w_kernel(const float* __restrict__ W1l, const float* __restrict__ W1r,
                              const float* __restrict__ W2l, const float* __restrict__ W2r)
{
    int t = blockIdx.x * blockDim.x + threadIdx.x;
    if (t >= 2 * 128 * 256) return;
    int layer = t >> 15;
    int rem = t & 32767;
    int nrow = rem >> 8;     // output column n
    int k = rem & 255;       // reduction index
    const float* Wl = layer ? W2l : W1l;
    const float* Wr = layer ? W2r : W1r;
    float v = (k < 128) ? __ldg(Wl + k * 128 + nrow) : __ldg(Wr + (k - 128) * 128 + nrow);
    __nv_bfloat16 hh = __float2bfloat16(v);
    __nv_bfloat16 ll = __float2bfloat16(v - __bfloat162float(hh));
    int ks = k >> 4, kp = k & 15;
    int pos = ks * 16 + 4 * ((kp & 7) >> 1) + 2 * (kp >> 3) + (kp & 1);
    uint32_t off = (uint32_t)(nrow * 272 + pos) * 2;
    *(__nv_bfloat16*)((char*)&g_wimg[layer][0][0] + off) = hh;
    *(__nv_bfloat16*)((char*)&g_wimg[layer][1][0] + off) = ll;
}

// ======================= Gather (mean aggregate) ===========================
__global__ void gather_kernel(const float* __restrict__ feat, int n)
{
    int lane = threadIdx.x & 31;
    int w = (blockIdx.x * blockDim.x + threadIdx.x) >> 5;
    if (w >= n) return;
    int start = g_rowptr[w];
    int cnt = g_degi[w];
    const float4* f4 = (const float4*)feat;
    float4 a0 = make_float4(0.f, 0.f, 0.f, 0.f), a1 = a0, a2 = a0, a3 = a0;
    int j = 0;
    for (; j + 4 <= cnt; j += 4) {
        int s0 = __ldg(g_csr + start + j);
        int s1 = __ldg(g_csr + start + j + 1);
        int s2 = __ldg(g_csr + start + j + 2);
        int s3 = __ldg(g_csr + start + j + 3);
        float4 v0 = __ldg(f4 + (size_t)s0 * 32 + lane);
        float4 v1 = __ldg(f4 + (size_t)s1 * 32 + lane);
        float4 v2 = __ldg(f4 + (size_t)s2 * 32 + lane);
        float4 v3 = __ldg(f4 + (size_t)s3 * 32 + lane);
        a0.x += v0.x; a0.y += v0.y; a0.z += v0.z; a0.w += v0.w;
        a1.x += v1.x; a1.y += v1.y; a1.z += v1.z; a1.w += v1.w;
        a2.x += v2.x; a2.y += v2.y; a2.z += v2.z; a2.w += v2.w;
        a3.x += v3.x; a3.y += v3.y; a3.z += v3.z; a3.w += v3.w;
    }
    for (; j < cnt; j++) {
        int s = __ldg(g_csr + start + j);
        float4 v = __ldg(f4 + (size_t)s * 32 + lane);
        a0.x += v.x; a0.y += v.y; a0.z += v.z; a0.w += v.w;
    }
    float inv = 1.0f / fmaxf((float)cnt, 1.0f);
    float4 rr;
    rr.x = (a0.x + a1.x + a2.x + a3.x) * inv;
    rr.y = (a0.y + a1.y + a2.y + a3.y) * inv;
    rr.z = (a0.z + a1.z + a2.z + a3.z) * inv;
    rr.w = (a0.w + a1.w + a2.w + a3.w) * inv;
    g_agg4[(size_t)w * 32 + lane] = rr;
}

// ======================= mma.sync GEMM =====================================
// C[i][0:128] = relu([agg_i | A2_i](256) @ W(256x128) + bias), bf16 split:
// A_hi*W_hi + A_lo*W_hi + A_hi*W_lo, fp32 accum.
// EPI==0: store C rows fp32.  EPI==1: out[i] = sigmoid(C[i].wfc + bfc).
#define OFF_W_HI 0
#define OFF_W_LO 69632
#define OFF_AH   139264
#define OFF_AL   180224
#define ABUF     20480
#define OFF_BIAS 221184
#define OFF_WFC  221696
#define OFF_FC   222208
#define MMA_SMEM 222720

template <int EPI>
__global__ __launch_bounds__(256, 1)
void mma_gemm_kernel(const float* __restrict__ A2, const uint4* __restrict__ wimg,
                     const float* __restrict__ bias, const float* __restrict__ wfc,
                     const float* __restrict__ bfc, float* __restrict__ out, int nn)
{
    extern __shared__ char smem[];
    uint32_t sb = smem_u32(smem);
    const int tid = threadIdx.x;
    const int lane = tid & 31, wid = tid >> 5;
    const int g = lane >> 2, t4 = lane & 3;
    const int wm = wid & 3, wn = wid >> 2;
    const int rowBase = blockIdx.x * 128;
    float* bias_s = (float*)(smem + OFF_BIAS);
    float* wfc_s  = (float*)(smem + OFF_WFC);
    float* fc_s   = (float*)(smem + OFF_FC);

    // stage W images (hi + lo contiguous: 8704 uint4)
    {
        uint4* dst = (uint4*)smem;
#pragma unroll
        for (int i = 0; i < 34; i++) {
            int idx = tid + 256 * i;
            dst[idx] = __ldg(wimg + idx);
        }
    }
    if (tid < 128) {
        bias_s[tid] = __ldg(bias + tid);
        wfc_s[tid] = EPI ? __ldg(wfc + tid) : 0.f;
        fc_s[tid] = 0.f;
    }

    const int r = tid >> 1, h = tid & 1;
    const int gr = rowBase + r;

    auto loadChunk = [&](int kc, float4* f) {
        const float* base = (kc < 2) ? (const float*)g_agg4 : A2;
        const float4* src = (const float4*)(base + (size_t)gr * 128 + (kc & 1) * 64) + h * 8;
#pragma unroll
        for (int j = 0; j < 8; j++)
            f[j] = (gr < nn) ? __ldg(src + j) : make_float4(0.f, 0.f, 0.f, 0.f);
    };
    auto storeChunk = [&](int buf, const float4* f) {
        uint32_t* ah = (uint32_t*)(smem + OFF_AH + buf * ABUF) + r * 40;
        uint32_t* al = (uint32_t*)(smem + OFF_AL + buf * ABUF) + r * 40;
#pragma unroll
        for (int j = 0; j < 8; j++) {
            float vv[4] = {f[j].x, f[j].y, f[j].z, f[j].w};
#pragma unroll
            for (int q = 0; q < 2; q++) {
                int p = h * 16 + j * 2 + q;
                int pp = p & 7, ks = p >> 3;
                int w = ks * 8 + ((pp < 4) ? 2 * pp : 2 * (pp - 4) + 1);
                float v0 = vv[2 * q], v1 = vv[2 * q + 1];
                __nv_bfloat16 h0 = __float2bfloat16(v0);
                __nv_bfloat16 h1 = __float2bfloat16(v1);
                __nv_bfloat162 hp = __halves2bfloat162(h0, h1);
                __nv_bfloat162 lp = __floats2bfloat162_rn(
                    v0 - __bfloat162float(h0), v1 - __bfloat162float(h1));
                ah[w] = *(uint32_t*)&hp;
                al[w] = *(uint32_t*)&lp;
            }
        }
    };

    float acc[2][8][4];
#pragma unroll
    for (int mi = 0; mi < 2; mi++)
#pragma unroll
        for (int ni = 0; ni < 8; ni++)
#pragma unroll
            for (int q = 0; q < 4; q++) acc[mi][ni][q] = 0.f;

    {
        float4 f0[8];
        loadChunk(0, f0);
        storeChunk(0, f0);
    }
    __syncthreads();

    for (int kc = 0; kc < 4; kc++) {
        float4 f[8];
        if (kc < 3) loadChunk(kc + 1, f);
        int buf = kc & 1;
        uint32_t ahB = sb + OFF_AH + buf * ABUF;
        uint32_t alB = sb + OFF_AL + buf * ABUF;
#pragma unroll
        for (int ks = 0; ks < 4; ks++) {
            int ksg = kc * 4 + ks;
            uint2 AH[2][2], AL[2][2];
#pragma unroll
            for (int mi = 0; mi < 2; mi++)
#pragma unroll
                for (int r8 = 0; r8 < 2; r8++) {
                    uint32_t ro = (uint32_t)(wm * 32 + mi * 16 + r8 * 8 + g) * 160
                                + ks * 32 + t4 * 8;
                    lds64(AH[mi][r8].x, AH[mi][r8].y, ahB + ro);
                    lds64(AL[mi][r8].x, AL[mi][r8].y, alB + ro);
                }
            uint2 BH[8], BL[8];
#pragma unroll
            for (int ni = 0; ni < 8; ni++) {
                uint32_t bo = (uint32_t)(wn * 64 + ni * 8 + g) * 544
                            + ksg * 32 + t4 * 8;
                lds64(BH[ni].x, BH[ni].y, sb + OFF_W_HI + bo);
                lds64(BL[ni].x, BL[ni].y, sb + OFF_W_LO + bo);
            }
#pragma unroll
            for (int mi = 0; mi < 2; mi++)
#pragma unroll
                for (int ni = 0; ni < 8; ni++) {
                    mma_bf16(acc[mi][ni], AH[mi][0].x, AH[mi][1].x,
                             AH[mi][0].y, AH[mi][1].y, BH[ni].x, BH[ni].y);
                    mma_bf16(acc[mi][ni], AL[mi][0].x, AL[mi][1].x,
                             AL[mi][0].y, AL[mi][1].y, BH[ni].x, BH[ni].y);
                    mma_bf16(acc[mi][ni], AH[mi][0].x, AH[mi][1].x,
                             AH[mi][0].y, AH[mi][1].y, BL[ni].x, BL[ni].y);
                }
        }
        if (kc < 3) storeChunk(1 - buf, f);
        __syncthreads();
    }

    // ---- epilogue ----
    if (EPI == 0) {
#pragma unroll
        for (int mi = 0; mi < 2; mi++)
#pragma unroll
            for (int ni = 0; ni < 8; ni++) {
                int rowA = rowBase + wm * 32 + mi * 16 + g;
                int nf = wn * 64 + ni * 8 + 2 * t4;
                float b0 = bias_s[nf], b1 = bias_s[nf + 1];
                float v0 = fmaxf(acc[mi][ni][0] + b0, 0.f);
                float v1 = fmaxf(acc[mi][ni][1] + b1, 0.f);
                float v2 = fmaxf(acc[mi][ni][2] + b0, 0.f);
                float v3 = fmaxf(acc[mi][ni][3] + b1, 0.f);
                if (rowA < nn)
                    *(float2*)(out + (size_t)rowA * 128 + nf) = make_float2(v0, v1);
                if (rowA + 8 < nn)
                    *(float2*)(out + (size_t)(rowA + 8) * 128 + nf) = make_float2(v2, v3);
            }
    } else {
#pragma unroll
        for (int mi = 0; mi < 2; mi++) {
            float pA = 0.f, pB = 0.f;
#pragma unroll
            for (int ni = 0; ni < 8; ni++) {
                int nf = wn * 64 + ni * 8 + 2 * t4;
                float b0 = bias_s[nf], b1 = bias_s[nf + 1];
                float w0 = wfc_s[nf], w1 = wfc_s[nf + 1];
                pA += fmaxf(acc[mi][ni][0] + b0, 0.f) * w0
                    + fmaxf(acc[mi][ni][1] + b1, 0.f) * w1;
                pB += fmaxf(acc[mi][ni][2] + b0, 0.f) * w0
                    + fmaxf(acc[mi][ni][3] + b1, 0.f) * w1;
            }
            pA += __shfl_xor_sync(0xffffffffu, pA, 1);
            pA += __shfl_xor_sync(0xffffffffu, pA, 2);
            pB += __shfl_xor_sync(0xffffffffu, pB, 1);
            pB += __shfl_xor_sync(0xffffffffu, pB, 2);
            if (t4 == 0) {
                atomicAdd(&fc_s[wm * 32 + mi * 16 + g], pA);
                atomicAdd(&fc_s[wm * 32 + mi * 16 + g + 8], pB);
            }
        }
        __syncthreads();
        if (tid < 128) {
            int row = rowBase + tid;
            if (row < nn)
                out[row] = 1.0f / (1.0f + __expf(-(fc_s[tid] + __ldg(bfc))));
        }
    }
}

// ======================= launch sequence ===================================
extern "C" void kernel_launch(void* const* d_in, const int* in_sizes, int n_in,
                              void* d_out, int out_size)
{
    const float* x   = (const float*)d_in[0];
    const void*  ei  = d_in[1];
    const float* W1l = (const float*)d_in[2];
    const float* W1r = (const float*)d_in[3];
    const float* b1  = (const float*)d_in[4];
    const float* W2l = (const float*)d_in[5];
    const float* W2r = (const float*)d_in[6];
    const float* b2  = (const float*)d_in[7];
    const float* Wfc = (const float*)d_in[8];
    const float* bfc = (const float*)d_in[9];
    float*       out = (float*)d_out;

    int n = in_sizes[0] / 128;
    int E = in_sizes[1] / 2;

    float* h1_ptr = nullptr;
    cudaGetSymbolAddress((void**)&h1_ptr, g_h14);
    uint4* wimg_ptr = nullptr;
    cudaGetSymbolAddress((void**)&wimg_ptr, g_wimg);

    cudaFuncSetAttribute(mma_gemm_kernel<0>,
                         cudaFuncAttributeMaxDynamicSharedMemorySize, MMA_SMEM);
    cudaFuncSetAttribute(mma_gemm_kernel<1>,
                         cudaFuncAttributeMaxDynamicSharedMemorySize, MMA_SMEM);

    int gemmBlocks = (n + 127) / 128;
    int nb = (n + 255) / 256;
    int gatherBlocks = (n * 32 + 255) / 256;

    // CSR build + W prep (once per call)
    probe_kernel<<<1, 1>>>(ei);
    zero_meta_kernel<<<nb, 256>>>(n);
    deg_kernel<<<1024, 256>>>(ei, E);
    block_sums_kernel<<<nb, 256>>>(n);
    scan_sums_kernel<<<1, 512>>>(nb);
    scan_block_kernel<<<nb, 256>>>(n);
    fill_kernel<<<1024, 256>>>(ei, E);
    prep_w_kernel<<<256, 256>>>(W1l, W1r, W2l, W2r);

    // layer 1
    gather_kernel<<<gatherBlocks, 256>>>(x, n);
    mma_gemm_kernel<0><<<gemmBlocks, 256, MMA_SMEM>>>(
        x, wimg_ptr, b1, nullptr, nullptr, h1_ptr, n);

    // layer 2 + FC head
    gather_kernel<<<gatherBlocks, 256>>>(h1_ptr, n);
    mma_gemm_kernel<1><<<gemmBlocks, 256, MMA_SMEM>>>(
        h1_ptr, wimg_ptr + 8704, b2, Wfc, bfc, out, n);
}